// round 13
// baseline (speedup 1.0000x reference)
#include <cuda_runtime.h>

typedef unsigned long long u64;

#define N_AGENTS 4096
#define TOPK 12
#define SEL 16
#define EPSC 1e-4f
#define TWPB 8                         // warps (rows) per topk block
#define BUFD 6
#define TOPK_BLOCKS (N_AGENTS / TWPB)  // 512

__device__ float2 g_W1p[6 * 32];        // [i][lane] -> W1 outputs lane, lane+32
__device__ float4 g_W2p4[64 * 32];      // [i][lane] -> W2 outputs lane+32q, q=0..3
__device__ float2 g_W3p[128 * 32];      // [i][lane] -> W3 outputs lane, lane+32
__device__ int    g_idx[N_AGENTS * TOPK];
__device__ float  g_dn [N_AGENTS * TOPK];

static __device__ __forceinline__ u64 umin64(u64 a, u64 b) { return a < b ? a : b; }
static __device__ __forceinline__ u64 pack2(float w) {
    u64 r; asm("mov.b64 %0, {%1, %1};" : "=l"(r) : "f"(w)); return r;
}
static __device__ __forceinline__ void ffma2(u64 &d, u64 a, u64 b) {
    asm("fma.rn.f32x2 %0, %1, %2, %0;" : "+l"(d) : "l"(a), "l"(b));
}
static __device__ __forceinline__ float2 unpack2(u64 v) {
    return make_float2(__uint_as_float((unsigned)v), __uint_as_float((unsigned)(v >> 32)));
}

// ============================ exact top-k (+trailing weight-pack block) ============================
static __device__ __forceinline__ void warp_merge(
    u64 &topent, u64 &thrkey, int &bcnt, u64 (*buf)[32], int lane)
{
    u64 v[BUFD];
#pragma unroll
    for (int s = 0; s < BUFD; s++) v[s] = (s < bcnt) ? buf[s][lane] : ~0ULL;
    u64 oldtop = topent;
    u64 newtop = ~0ULL;
#pragma unroll 1
    for (int r = 0; r < SEL; r++) {
        u64 lm = oldtop;
#pragma unroll
        for (int s = 0; s < BUFD; s++) lm = umin64(lm, v[s]);
#pragma unroll
        for (int o = 16; o > 0; o >>= 1)
            lm = umin64(lm, __shfl_xor_sync(0xffffffffu, lm, o));
        if (oldtop == lm) oldtop = ~0ULL;
#pragma unroll
        for (int s = 0; s < BUFD; s++) if (v[s] == lm) v[s] = ~0ULL;
        if (lane == r) newtop = lm;
        thrkey = lm;
    }
    topent = newtop;
    bcnt = 0;
}

__global__ __launch_bounds__(32 * TWPB) void topk_kernel(
    const float4* __restrict__ states,
    const float* __restrict__ W1, const float* __restrict__ W2,
    const float* __restrict__ W3)
{
    // trailing block: pack weights (touches nothing the topk blocks read)
    if (blockIdx.x == TOPK_BLOCKS) {
        for (int t = threadIdx.x; t < 4096; t += 32 * TWPB) {
            int i = t >> 5, lane = t & 31;
            g_W3p[t] = make_float2(W3[lane * 128 + i], W3[(lane + 32) * 128 + i]);
            if (t < 2048)
                g_W2p4[t] = make_float4(W2[lane * 64 + i],        W2[(lane + 32) * 64 + i],
                                        W2[(lane + 64) * 64 + i], W2[(lane + 96) * 64 + i]);
            if (t < 192)
                g_W1p[t] = make_float2(W1[lane * 6 + i], W1[(lane + 32) * 6 + i]);
        }
        return;
    }

    __shared__ float2 sxy[N_AGENTS];       // 32 KB, packed (x,y)
    __shared__ u64 sbuf[TWPB][BUFD][32];   // 12 KB

    for (int j = threadIdx.x; j < N_AGENTS; j += 32 * TWPB) {
        float4 s = states[j];
        sxy[j] = make_float2(s.x, s.y);
    }
    __syncthreads();

    const int warp = threadIdx.x >> 5;
    const int lane = threadIdx.x & 31;
    const int row  = blockIdx.x * TWPB + warp;
    const float xi = sxy[row].x, yi = sxy[row].y;
    const float4* xy4 = reinterpret_cast<const float4*>(sxy);

    u64 topent = ~0ULL, thrkey = ~0ULL;
    int bcnt = 0;

    // ---- warm start: exact top-16 of first 64 candidates, tight threshold ----
    {
        float4 p = xy4[lane];
        int j0 = 2 * lane;
        float dx0 = __fsub_rn(xi, p.x);
        float dy0 = __fsub_rn(yi, p.y);
        float d20 = __fadd_rn(__fadd_rn(__fmul_rn(dx0, dx0), EPSC),
                              __fadd_rn(__fmul_rn(dy0, dy0), EPSC));
        float dx1 = __fsub_rn(xi, p.z);
        float dy1 = __fsub_rn(yi, p.w);
        float d21 = __fadd_rn(__fadd_rn(__fmul_rn(dx1, dx1), EPSC),
                              __fadd_rn(__fmul_rn(dy1, dy1), EPSC));
        topent = ((u64)__float_as_uint(d20) << 32) | (unsigned)j0;
        sbuf[warp][0][lane] = ((u64)__float_as_uint(d21) << 32) | (unsigned)(j0 + 1);
        bcnt = 1;
        warp_merge(topent, thrkey, bcnt, sbuf[warp], lane);
    }
    // float threshold: d2 <= thrf is a conservative-exact push filter
    // (d2 > 0 so float bits are monotone; equal-d2 extras are culled by the merge)
    float thrf = __uint_as_float((unsigned)(thrkey >> 32));

#pragma unroll 1
    for (int m = 1; m < N_AGENTS / 64; m++) {
        float4 p = xy4[m * 32 + lane];         // candidates j0, j0+1
        int j0 = m * 64 + 2 * lane;
        float dx0 = __fsub_rn(xi, p.x);
        float dy0 = __fsub_rn(yi, p.y);
        float d20 = __fadd_rn(__fadd_rn(__fmul_rn(dx0, dx0), EPSC),
                              __fadd_rn(__fmul_rn(dy0, dy0), EPSC));
        float dx1 = __fsub_rn(xi, p.z);
        float dy1 = __fsub_rn(yi, p.w);
        float d21 = __fadd_rn(__fadd_rn(__fmul_rn(dx1, dx1), EPSC),
                              __fadd_rn(__fmul_rn(dy1, dy1), EPSC));
        if (d20 <= thrf) {
            sbuf[warp][bcnt][lane] =
                ((u64)__float_as_uint(d20) << 32) | (unsigned)j0;
            bcnt++;
        }
        if (d21 <= thrf) {
            sbuf[warp][bcnt][lane] =
                ((u64)__float_as_uint(d21) << 32) | (unsigned)(j0 + 1);
            bcnt++;
        }
        if (__ballot_sync(0xffffffffu, bcnt > BUFD - 2)) {
            warp_merge(topent, thrkey, bcnt, sbuf[warp], lane);
            thrf = __uint_as_float((unsigned)(thrkey >> 32));
        }
    }
    if (__ballot_sync(0xffffffffu, bcnt > 0))
        warp_merge(topent, thrkey, bcnt, sbuf[warp], lane);

    // re-rank survivors by (dn, idx) — JAX top_k tie semantics
    float d2v = __uint_as_float((unsigned)(topent >> 32));
    int   jv  = (int)(unsigned)(topent & 0xffffffffu);
    float dnv = __fsqrt_rn(d2v);
    int rank = 0;
#pragma unroll
    for (int ml = 0; ml < SEL; ml++) {
        float dm = __shfl_sync(0xffffffffu, dnv, ml);
        int   jm = __shfl_sync(0xffffffffu, jv,  ml);
        if (ml != lane && (dm < dnv || (dm == dnv && jm < jv))) rank++;
    }
    if (lane < SEL && rank < TOPK) {
        g_idx[row * TOPK + rank] = jv;
        g_dn [row * TOPK + rank] = dnv;
    }
}

// ============ MLP: full agent per warp, single-pass layer 2, 6 CTAs/SM ============
#define WARP_FLOATS 2376
__global__ __launch_bounds__(128, 6) void mlp_kernel(
    const float4* __restrict__ states,
    const float* __restrict__ b1, const float* __restrict__ b2,
    const float* __restrict__ b3,
    const float* __restrict__ W4, const float* __restrict__ b4,
    float* __restrict__ out, int out_size)
{
    __shared__ alignas(16) float smem[4][WARP_FLOATS];   // 38016 B total
    const int t = threadIdx.x;
    const int w = t >> 5;
    const int lane = t & 31;
    const int a = blockIdx.x * 4 + w;

    float* zB = smem[w];           // [128][12]; aliases: xs [12][8] (early), z3t [12][68] (late)
    float* zA = smem[w] + 1536;    // [64][12]
    float* A1 = smem[w] + 2304;    // [6][12]
    float* xs = zB;                // staging (dead before zB written)
    float* z3t = zB;

    float maskr = 0.0f;
    if (lane < TOPK) {
        int   idx = g_idx[a * TOPK + lane];
        float dn  = g_dn [a * TOPK + lane];
        float4 si = states[a];
        float4 sj = states[idx];
        xs[lane * 8 + 0] = __fsub_rn(si.x, sj.x);
        xs[lane * 8 + 1] = __fsub_rn(si.y, sj.y);
        xs[lane * 8 + 2] = __fsub_rn(si.z, sj.z);
        xs[lane * 8 + 3] = __fsub_rn(si.w, sj.w);
        xs[lane * 8 + 4] = (idx == a) ? 1.0f : 0.0f;
        xs[lane * 8 + 5] = __fsub_rn(dn, 0.8f);
        maskr = (dn <= 1.0f) ? 1.0f : 0.0f;
    }
    __syncwarp();
    // scrambled reshape: h0[i][l] = xs[2i + l/6][l % 6]
    if (lane < TOPK) {
        int half = lane / 6, cc = lane % 6;
#pragma unroll
        for (int i = 0; i < 6; i++)
            A1[i * 12 + lane] = xs[(2 * i + half) * 8 + cc];
    }
    __syncwarp();

    // ---- layer 1: 6 -> 64, 2 outputs/lane ----
    {
        u64 acc[12];
        u64 bb0 = pack2(b1[lane]), bb1 = pack2(b1[lane + 32]);
#pragma unroll
        for (int p = 0; p < 6; p++) { acc[p] = bb0; acc[6 + p] = bb1; }
#pragma unroll
        for (int i = 0; i < 6; i++) {
            float2 wv = g_W1p[i * 32 + lane];
            u64 w0 = pack2(wv.x), w1 = pack2(wv.y);
            const ulonglong2* r = reinterpret_cast<const ulonglong2*>(A1 + i * 12);
            ulonglong2 q0 = r[0], q1 = r[1], q2 = r[2];
            ffma2(acc[0], w0, q0.x); ffma2(acc[1], w0, q0.y);
            ffma2(acc[2], w0, q1.x); ffma2(acc[3], w0, q1.y);
            ffma2(acc[4], w0, q2.x); ffma2(acc[5], w0, q2.y);
            ffma2(acc[6], w1, q0.x); ffma2(acc[7], w1, q0.y);
            ffma2(acc[8], w1, q1.x); ffma2(acc[9], w1, q1.y);
            ffma2(acc[10], w1, q2.x); ffma2(acc[11], w1, q2.y);
        }
        float2* zA2 = reinterpret_cast<float2*>(zA);
#pragma unroll
        for (int p = 0; p < 6; p++) {
            float2 u = unpack2(acc[p]);
            zA2[lane * 6 + p] = make_float2(fmaxf(u.x, 0.f), fmaxf(u.y, 0.f));
            float2 v = unpack2(acc[6 + p]);
            zA2[(lane + 32) * 6 + p] = make_float2(fmaxf(v.x, 0.f), fmaxf(v.y, 0.f));
        }
    }
    __syncwarp();   // xs dead; zB writable

    // ---- layer 2: 64 -> 128, 4 outputs/lane, single pass ----
    {
        u64 acc[24];
#pragma unroll
        for (int q = 0; q < 4; q++) {
            u64 bb = pack2(b2[lane + 32 * q]);
#pragma unroll
            for (int p = 0; p < 6; p++) acc[q * 6 + p] = bb;
        }
#pragma unroll 2
        for (int i = 0; i < 64; i++) {
            float4 wv = g_W2p4[i * 32 + lane];
            u64 w0 = pack2(wv.x), w1 = pack2(wv.y), w2 = pack2(wv.z), w3 = pack2(wv.w);
            const ulonglong2* r = reinterpret_cast<const ulonglong2*>(zA + i * 12);
            ulonglong2 q0 = r[0], q1 = r[1], q2 = r[2];
            ffma2(acc[0],  w0, q0.x); ffma2(acc[1],  w0, q0.y);
            ffma2(acc[2],  w0, q1.x); ffma2(acc[3],  w0, q1.y);
            ffma2(acc[4],  w0, q2.x); ffma2(acc[5],  w0, q2.y);
            ffma2(acc[6],  w1, q0.x); ffma2(acc[7],  w1, q0.y);
            ffma2(acc[8],  w1, q1.x); ffma2(acc[9],  w1, q1.y);
            ffma2(acc[10], w1, q2.x); ffma2(acc[11], w1, q2.y);
            ffma2(acc[12], w2, q0.x); ffma2(acc[13], w2, q0.y);
            ffma2(acc[14], w2, q1.x); ffma2(acc[15], w2, q1.y);
            ffma2(acc[16], w2, q2.x); ffma2(acc[17], w2, q2.y);
            ffma2(acc[18], w3, q0.x); ffma2(acc[19], w3, q0.y);
            ffma2(acc[20], w3, q1.x); ffma2(acc[21], w3, q1.y);
            ffma2(acc[22], w3, q2.x); ffma2(acc[23], w3, q2.y);
        }
        float2* zB2 = reinterpret_cast<float2*>(zB);
#pragma unroll
        for (int q = 0; q < 4; q++) {
#pragma unroll
            for (int p = 0; p < 6; p++) {
                float2 u = unpack2(acc[q * 6 + p]);
                zB2[(lane + 32 * q) * 6 + p] =
                    make_float2(fmaxf(u.x, 0.f), fmaxf(u.y, 0.f));
            }
        }
    }
    __syncwarp();

    // ---- layer 3: 128 -> 64, 2 outputs/lane; store transposed z3t[12][68] ----
    {
        u64 acc[12];
        u64 bb0 = pack2(b3[lane]), bb1 = pack2(b3[lane + 32]);
#pragma unroll
        for (int p = 0; p < 6; p++) { acc[p] = bb0; acc[6 + p] = bb1; }
#pragma unroll 2
        for (int i = 0; i < 128; i++) {
            float2 wv = g_W3p[i * 32 + lane];
            u64 w0 = pack2(wv.x), w1 = pack2(wv.y);
            const ulonglong2* r = reinterpret_cast<const ulonglong2*>(zB + i * 12);
            ulonglong2 q0 = r[0], q1 = r[1], q2 = r[2];
            ffma2(acc[0], w0, q0.x); ffma2(acc[1], w0, q0.y);
            ffma2(acc[2], w0, q1.x); ffma2(acc[3], w0, q1.y);
            ffma2(acc[4], w0, q2.x); ffma2(acc[5], w0, q2.y);
            ffma2(acc[6], w1, q0.x); ffma2(acc[7], w1, q0.y);
            ffma2(acc[8], w1, q1.x); ffma2(acc[9], w1, q1.y);
            ffma2(acc[10], w1, q2.x); ffma2(acc[11], w1, q2.y);
        }
        __syncwarp();   // all zB reads done before z3t (alias) stores
#pragma unroll
        for (int p = 0; p < 6; p++) {
            float2 u = unpack2(acc[p]);
            z3t[(2 * p)     * 68 + lane] = fmaxf(u.x, 0.f);
            z3t[(2 * p + 1) * 68 + lane] = fmaxf(u.y, 0.f);
            float2 v = unpack2(acc[6 + p]);
            z3t[(2 * p)     * 68 + lane + 32] = fmaxf(v.x, 0.f);
            z3t[(2 * p + 1) * 68 + lane + 32] = fmaxf(v.y, 0.f);
        }
    }
    __syncwarp();

    // ---- layer 4: 64 -> 1 per column, mask, write ----
    if (lane < TOPK) {
        const float4* zv = reinterpret_cast<const float4*>(z3t + lane * 68);
        const float4* wv = reinterpret_cast<const float4*>(W4);
        float a0 = b4[0], a1 = 0.f, a2 = 0.f, a3 = 0.f;
#pragma unroll
        for (int oc = 0; oc < 16; oc++) {
            float4 z = zv[oc];
            float4 ww = wv[oc];
            a0 = fmaf(ww.x, z.x, a0);
            a1 = fmaf(ww.y, z.y, a1);
            a2 = fmaf(ww.z, z.z, a2);
            a3 = fmaf(ww.w, z.w, a3);
        }
        float acc = (a0 + a1) + (a2 + a3);
        out[a * TOPK + lane] = acc * maskr;
        if (out_size >= 2 * N_AGENTS * TOPK)
            out[N_AGENTS * TOPK + a * TOPK + lane] = maskr;
    }
}

extern "C" void kernel_launch(void* const* d_in, const int* in_sizes, int n_in,
                              void* d_out, int out_size) {
    const float* states = (const float*)d_in[0];
    const float* W1 = (const float*)d_in[1];
    const float* b1 = (const float*)d_in[2];
    const float* W2 = (const float*)d_in[3];
    const float* b2 = (const float*)d_in[4];
    const float* W3 = (const float*)d_in[5];
    const float* b3 = (const float*)d_in[6];
    const float* W4 = (const float*)d_in[7];
    const float* b4 = (const float*)d_in[8];
    float* out = (float*)d_out;

    topk_kernel<<<TOPK_BLOCKS + 1, 32 * TWPB>>>((const float4*)states, W1, W2, W3);
    mlp_kernel<<<N_AGENTS / 4, 128>>>((const float4*)states,
                                      b1, b2, b3, W4, b4, out, out_size);
}

// round 14
// speedup vs baseline: 1.0061x; 1.0061x over previous
#include <cuda_runtime.h>

typedef unsigned long long u64;

#define N_AGENTS 4096
#define TOPK 12
#define SEL 16
#define EPSC 1e-4f
#define TWPB 8                         // warps (rows) per topk block
#define BUFD 6
#define TOPK_BLOCKS (N_AGENTS / TWPB)  // 512

__device__ float2 g_W1p[6 * 32];        // [i][lane] -> W1 outputs lane, lane+32
__device__ float4 g_W2p4[64 * 32];      // [i][lane] -> W2 outputs lane+32q, q=0..3
__device__ float2 g_W3p[128 * 32];      // [i][lane] -> W3 outputs lane, lane+32
__device__ int    g_idx[N_AGENTS * TOPK];
__device__ float  g_dn [N_AGENTS * TOPK];

static __device__ __forceinline__ u64 umin64(u64 a, u64 b) { return a < b ? a : b; }
static __device__ __forceinline__ u64 pack2(float w) {
    u64 r; asm("mov.b64 %0, {%1, %1};" : "=l"(r) : "f"(w)); return r;
}
static __device__ __forceinline__ void ffma2(u64 &d, u64 a, u64 b) {
    asm("fma.rn.f32x2 %0, %1, %2, %0;" : "+l"(d) : "l"(a), "l"(b));
}
static __device__ __forceinline__ float2 unpack2(u64 v) {
    return make_float2(__uint_as_float((unsigned)v), __uint_as_float((unsigned)(v >> 32)));
}

// ============================ exact top-k (+trailing weight-pack block) ============================
static __device__ __forceinline__ void warp_merge(
    u64 &topent, u64 &thrkey, int &bcnt, u64 (*buf)[32], int lane)
{
    u64 v[BUFD];
#pragma unroll
    for (int s = 0; s < BUFD; s++) v[s] = (s < bcnt) ? buf[s][lane] : ~0ULL;
    u64 oldtop = topent;
    u64 newtop = ~0ULL;
#pragma unroll 1
    for (int r = 0; r < SEL; r++) {
        u64 lm = oldtop;
#pragma unroll
        for (int s = 0; s < BUFD; s++) lm = umin64(lm, v[s]);
#pragma unroll
        for (int o = 16; o > 0; o >>= 1)
            lm = umin64(lm, __shfl_xor_sync(0xffffffffu, lm, o));
        if (oldtop == lm) oldtop = ~0ULL;
#pragma unroll
        for (int s = 0; s < BUFD; s++) if (v[s] == lm) v[s] = ~0ULL;
        if (lane == r) newtop = lm;
        thrkey = lm;
    }
    topent = newtop;
    bcnt = 0;
}

__global__ __launch_bounds__(32 * TWPB) void topk_kernel(
    const float4* __restrict__ states,
    const float* __restrict__ W1, const float* __restrict__ W2,
    const float* __restrict__ W3)
{
    // trailing block: pack weights (touches nothing the topk blocks read)
    if (blockIdx.x == TOPK_BLOCKS) {
        for (int t = threadIdx.x; t < 4096; t += 32 * TWPB) {
            int i = t >> 5, lane = t & 31;
            g_W3p[t] = make_float2(W3[lane * 128 + i], W3[(lane + 32) * 128 + i]);
            if (t < 2048)
                g_W2p4[t] = make_float4(W2[lane * 64 + i],        W2[(lane + 32) * 64 + i],
                                        W2[(lane + 64) * 64 + i], W2[(lane + 96) * 64 + i]);
            if (t < 192)
                g_W1p[t] = make_float2(W1[lane * 6 + i], W1[(lane + 32) * 6 + i]);
        }
        return;
    }

    __shared__ float2 sxy[N_AGENTS];       // 32 KB, packed (x,y)
    __shared__ u64 sbuf[TWPB][BUFD][32];   // 12 KB

    for (int j = threadIdx.x; j < N_AGENTS; j += 32 * TWPB) {
        float4 s = states[j];
        sxy[j] = make_float2(s.x, s.y);
    }
    __syncthreads();

    const int warp = threadIdx.x >> 5;
    const int lane = threadIdx.x & 31;
    const int row  = blockIdx.x * TWPB + warp;
    const float xi = sxy[row].x, yi = sxy[row].y;
    const float4* xy4 = reinterpret_cast<const float4*>(sxy);

    u64 topent = ~0ULL, thrkey = ~0ULL;
    int bcnt = 0;

    // ---- warm start: exact top-16 of first 64 candidates, tight threshold ----
    {
        float4 p = xy4[lane];
        int j0 = 2 * lane;
        float dx0 = __fsub_rn(xi, p.x);
        float dy0 = __fsub_rn(yi, p.y);
        float d20 = __fadd_rn(__fadd_rn(__fmul_rn(dx0, dx0), EPSC),
                              __fadd_rn(__fmul_rn(dy0, dy0), EPSC));
        float dx1 = __fsub_rn(xi, p.z);
        float dy1 = __fsub_rn(yi, p.w);
        float d21 = __fadd_rn(__fadd_rn(__fmul_rn(dx1, dx1), EPSC),
                              __fadd_rn(__fmul_rn(dy1, dy1), EPSC));
        topent = ((u64)__float_as_uint(d20) << 32) | (unsigned)j0;
        sbuf[warp][0][lane] = ((u64)__float_as_uint(d21) << 32) | (unsigned)(j0 + 1);
        bcnt = 1;
        warp_merge(topent, thrkey, bcnt, sbuf[warp], lane);
    }
    // float threshold: d2 <= thrf is a conservative-exact push filter
    // (d2 > 0 so float bits are monotone; equal-d2 extras are culled by the merge)
    float thrf = __uint_as_float((unsigned)(thrkey >> 32));

#pragma unroll 1
    for (int m = 1; m < N_AGENTS / 64; m++) {
        float4 p = xy4[m * 32 + lane];         // candidates j0, j0+1
        int j0 = m * 64 + 2 * lane;
        float dx0 = __fsub_rn(xi, p.x);
        float dy0 = __fsub_rn(yi, p.y);
        float d20 = __fadd_rn(__fadd_rn(__fmul_rn(dx0, dx0), EPSC),
                              __fadd_rn(__fmul_rn(dy0, dy0), EPSC));
        float dx1 = __fsub_rn(xi, p.z);
        float dy1 = __fsub_rn(yi, p.w);
        float d21 = __fadd_rn(__fadd_rn(__fmul_rn(dx1, dx1), EPSC),
                              __fadd_rn(__fmul_rn(dy1, dy1), EPSC));
        if (d20 <= thrf) {
            sbuf[warp][bcnt][lane] =
                ((u64)__float_as_uint(d20) << 32) | (unsigned)j0;
            bcnt++;
        }
        if (d21 <= thrf) {
            sbuf[warp][bcnt][lane] =
                ((u64)__float_as_uint(d21) << 32) | (unsigned)(j0 + 1);
            bcnt++;
        }
        if (__ballot_sync(0xffffffffu, bcnt > BUFD - 2)) {
            warp_merge(topent, thrkey, bcnt, sbuf[warp], lane);
            thrf = __uint_as_float((unsigned)(thrkey >> 32));
        }
    }
    if (__ballot_sync(0xffffffffu, bcnt > 0))
        warp_merge(topent, thrkey, bcnt, sbuf[warp], lane);

    // re-rank survivors by (dn, idx) — JAX top_k tie semantics
    float d2v = __uint_as_float((unsigned)(topent >> 32));
    int   jv  = (int)(unsigned)(topent & 0xffffffffu);
    float dnv = __fsqrt_rn(d2v);
    int rank = 0;
#pragma unroll
    for (int ml = 0; ml < SEL; ml++) {
        float dm = __shfl_sync(0xffffffffu, dnv, ml);
        int   jm = __shfl_sync(0xffffffffu, jv,  ml);
        if (ml != lane && (dm < dnv || (dm == dnv && jm < jv))) rank++;
    }
    if (lane < SEL && rank < TOPK) {
        g_idx[row * TOPK + rank] = jv;
        g_dn [row * TOPK + rank] = dnv;
    }
}

// ============ MLP: full agent per warp, single-pass layer 2 (R12 verbatim) ============
#define WARP_FLOATS 2376
__global__ __launch_bounds__(128) void mlp_kernel(
    const float4* __restrict__ states,
    const float* __restrict__ b1, const float* __restrict__ b2,
    const float* __restrict__ b3,
    const float* __restrict__ W4, const float* __restrict__ b4,
    float* __restrict__ out, int out_size)
{
    __shared__ alignas(16) float smem[4][WARP_FLOATS];   // 38016 B total
    const int t = threadIdx.x;
    const int w = t >> 5;
    const int lane = t & 31;
    const int a = blockIdx.x * 4 + w;

    float* zB = smem[w];           // [128][12]; aliases: xs [12][8] (early), z3t [12][68] (late)
    float* zA = smem[w] + 1536;    // [64][12]
    float* A1 = smem[w] + 2304;    // [6][12]
    float* xs = zB;                // staging (dead before zB written)
    float* z3t = zB;

    float maskr = 0.0f;
    if (lane < TOPK) {
        int   idx = g_idx[a * TOPK + lane];
        float dn  = g_dn [a * TOPK + lane];
        float4 si = states[a];
        float4 sj = states[idx];
        xs[lane * 8 + 0] = __fsub_rn(si.x, sj.x);
        xs[lane * 8 + 1] = __fsub_rn(si.y, sj.y);
        xs[lane * 8 + 2] = __fsub_rn(si.z, sj.z);
        xs[lane * 8 + 3] = __fsub_rn(si.w, sj.w);
        xs[lane * 8 + 4] = (idx == a) ? 1.0f : 0.0f;
        xs[lane * 8 + 5] = __fsub_rn(dn, 0.8f);
        maskr = (dn <= 1.0f) ? 1.0f : 0.0f;
    }
    __syncwarp();
    // scrambled reshape: h0[i][l] = xs[2i + l/6][l % 6]
    if (lane < TOPK) {
        int half = lane / 6, cc = lane % 6;
#pragma unroll
        for (int i = 0; i < 6; i++)
            A1[i * 12 + lane] = xs[(2 * i + half) * 8 + cc];
    }
    __syncwarp();

    // ---- layer 1: 6 -> 64, 2 outputs/lane ----
    {
        u64 acc[12];
        u64 bb0 = pack2(b1[lane]), bb1 = pack2(b1[lane + 32]);
#pragma unroll
        for (int p = 0; p < 6; p++) { acc[p] = bb0; acc[6 + p] = bb1; }
#pragma unroll
        for (int i = 0; i < 6; i++) {
            float2 wv = g_W1p[i * 32 + lane];
            u64 w0 = pack2(wv.x), w1 = pack2(wv.y);
            const ulonglong2* r = reinterpret_cast<const ulonglong2*>(A1 + i * 12);
            ulonglong2 q0 = r[0], q1 = r[1], q2 = r[2];
            ffma2(acc[0], w0, q0.x); ffma2(acc[1], w0, q0.y);
            ffma2(acc[2], w0, q1.x); ffma2(acc[3], w0, q1.y);
            ffma2(acc[4], w0, q2.x); ffma2(acc[5], w0, q2.y);
            ffma2(acc[6], w1, q0.x); ffma2(acc[7], w1, q0.y);
            ffma2(acc[8], w1, q1.x); ffma2(acc[9], w1, q1.y);
            ffma2(acc[10], w1, q2.x); ffma2(acc[11], w1, q2.y);
        }
        float2* zA2 = reinterpret_cast<float2*>(zA);
#pragma unroll
        for (int p = 0; p < 6; p++) {
            float2 u = unpack2(acc[p]);
            zA2[lane * 6 + p] = make_float2(fmaxf(u.x, 0.f), fmaxf(u.y, 0.f));
            float2 v = unpack2(acc[6 + p]);
            zA2[(lane + 32) * 6 + p] = make_float2(fmaxf(v.x, 0.f), fmaxf(v.y, 0.f));
        }
    }
    __syncwarp();   // xs dead; zB writable

    // ---- layer 2: 64 -> 128, 4 outputs/lane, single pass ----
    {
        u64 acc[24];
#pragma unroll
        for (int q = 0; q < 4; q++) {
            u64 bb = pack2(b2[lane + 32 * q]);
#pragma unroll
            for (int p = 0; p < 6; p++) acc[q * 6 + p] = bb;
        }
#pragma unroll 2
        for (int i = 0; i < 64; i++) {
            float4 wv = g_W2p4[i * 32 + lane];
            u64 w0 = pack2(wv.x), w1 = pack2(wv.y), w2 = pack2(wv.z), w3 = pack2(wv.w);
            const ulonglong2* r = reinterpret_cast<const ulonglong2*>(zA + i * 12);
            ulonglong2 q0 = r[0], q1 = r[1], q2 = r[2];
            ffma2(acc[0],  w0, q0.x); ffma2(acc[1],  w0, q0.y);
            ffma2(acc[2],  w0, q1.x); ffma2(acc[3],  w0, q1.y);
            ffma2(acc[4],  w0, q2.x); ffma2(acc[5],  w0, q2.y);
            ffma2(acc[6],  w1, q0.x); ffma2(acc[7],  w1, q0.y);
            ffma2(acc[8],  w1, q1.x); ffma2(acc[9],  w1, q1.y);
            ffma2(acc[10], w1, q2.x); ffma2(acc[11], w1, q2.y);
            ffma2(acc[12], w2, q0.x); ffma2(acc[13], w2, q0.y);
            ffma2(acc[14], w2, q1.x); ffma2(acc[15], w2, q1.y);
            ffma2(acc[16], w2, q2.x); ffma2(acc[17], w2, q2.y);
            ffma2(acc[18], w3, q0.x); ffma2(acc[19], w3, q0.y);
            ffma2(acc[20], w3, q1.x); ffma2(acc[21], w3, q1.y);
            ffma2(acc[22], w3, q2.x); ffma2(acc[23], w3, q2.y);
        }
        float2* zB2 = reinterpret_cast<float2*>(zB);
#pragma unroll
        for (int q = 0; q < 4; q++) {
#pragma unroll
            for (int p = 0; p < 6; p++) {
                float2 u = unpack2(acc[q * 6 + p]);
                zB2[(lane + 32 * q) * 6 + p] =
                    make_float2(fmaxf(u.x, 0.f), fmaxf(u.y, 0.f));
            }
        }
    }
    __syncwarp();

    // ---- layer 3: 128 -> 64, 2 outputs/lane; store transposed z3t[12][68] ----
    {
        u64 acc[12];
        u64 bb0 = pack2(b3[lane]), bb1 = pack2(b3[lane + 32]);
#pragma unroll
        for (int p = 0; p < 6; p++) { acc[p] = bb0; acc[6 + p] = bb1; }
#pragma unroll 2
        for (int i = 0; i < 128; i++) {
            float2 wv = g_W3p[i * 32 + lane];
            u64 w0 = pack2(wv.x), w1 = pack2(wv.y);
            const ulonglong2* r = reinterpret_cast<const ulonglong2*>(zB + i * 12);
            ulonglong2 q0 = r[0], q1 = r[1], q2 = r[2];
            ffma2(acc[0], w0, q0.x); ffma2(acc[1], w0, q0.y);
            ffma2(acc[2], w0, q1.x); ffma2(acc[3], w0, q1.y);
            ffma2(acc[4], w0, q2.x); ffma2(acc[5], w0, q2.y);
            ffma2(acc[6], w1, q0.x); ffma2(acc[7], w1, q0.y);
            ffma2(acc[8], w1, q1.x); ffma2(acc[9], w1, q1.y);
            ffma2(acc[10], w1, q2.x); ffma2(acc[11], w1, q2.y);
        }
        __syncwarp();   // all zB reads done before z3t (alias) stores
#pragma unroll
        for (int p = 0; p < 6; p++) {
            float2 u = unpack2(acc[p]);
            z3t[(2 * p)     * 68 + lane] = fmaxf(u.x, 0.f);
            z3t[(2 * p + 1) * 68 + lane] = fmaxf(u.y, 0.f);
            float2 v = unpack2(acc[6 + p]);
            z3t[(2 * p)     * 68 + lane + 32] = fmaxf(v.x, 0.f);
            z3t[(2 * p + 1) * 68 + lane + 32] = fmaxf(v.y, 0.f);
        }
    }
    __syncwarp();

    // ---- layer 4: 64 -> 1 per column, mask, write ----
    if (lane < TOPK) {
        const float4* zv = reinterpret_cast<const float4*>(z3t + lane * 68);
        const float4* wv = reinterpret_cast<const float4*>(W4);
        float a0 = b4[0], a1 = 0.f, a2 = 0.f, a3 = 0.f;
#pragma unroll
        for (int oc = 0; oc < 16; oc++) {
            float4 z = zv[oc];
            float4 ww = wv[oc];
            a0 = fmaf(ww.x, z.x, a0);
            a1 = fmaf(ww.y, z.y, a1);
            a2 = fmaf(ww.z, z.z, a2);
            a3 = fmaf(ww.w, z.w, a3);
        }
        float acc = (a0 + a1) + (a2 + a3);
        out[a * TOPK + lane] = acc * maskr;
        if (out_size >= 2 * N_AGENTS * TOPK)
            out[N_AGENTS * TOPK + a * TOPK + lane] = maskr;
    }
}

extern "C" void kernel_launch(void* const* d_in, const int* in_sizes, int n_in,
                              void* d_out, int out_size) {
    const float* states = (const float*)d_in[0];
    const float* W1 = (const float*)d_in[1];
    const float* b1 = (const float*)d_in[2];
    const float* W2 = (const float*)d_in[3];
    const float* b2 = (const float*)d_in[4];
    const float* W3 = (const float*)d_in[5];
    const float* b3 = (const float*)d_in[6];
    const float* W4 = (const float*)d_in[7];
    const float* b4 = (const float*)d_in[8];
    float* out = (float*)d_out;

    topk_kernel<<<TOPK_BLOCKS + 1, 32 * TWPB>>>((const float4*)states, W1, W2, W3);
    mlp_kernel<<<N_AGENTS / 4, 128>>>((const float4*)states,
                                      b1, b2, b3, W4, b4, out, out_size);
}

// round 15
// speedup vs baseline: 1.0184x; 1.0123x over previous
#include <cuda_runtime.h>

typedef unsigned long long u64;

#define N_AGENTS 4096
#define TOPK 12
#define SEL 16
#define EPSC 1e-4f
#define TWPB 8                         // warps (rows) per topk block
#define BUFD 8
#define TOPK_BLOCKS (N_AGENTS / TWPB)  // 512

__device__ float2 g_W1p[6 * 32];        // [i][lane] -> W1 outputs lane, lane+32
__device__ float4 g_W2p4[64 * 32];      // [i][lane] -> W2 outputs lane+32q, q=0..3
__device__ float2 g_W3p[128 * 32];      // [i][lane] -> W3 outputs lane, lane+32
__device__ int    g_idx[N_AGENTS * TOPK];
__device__ float  g_dn [N_AGENTS * TOPK];

static __device__ __forceinline__ u64 umin64(u64 a, u64 b) { return a < b ? a : b; }
static __device__ __forceinline__ u64 pack2(float w) {
    u64 r; asm("mov.b64 %0, {%1, %1};" : "=l"(r) : "f"(w)); return r;
}
static __device__ __forceinline__ void ffma2(u64 &d, u64 a, u64 b) {
    asm("fma.rn.f32x2 %0, %1, %2, %0;" : "+l"(d) : "l"(a), "l"(b));
}
static __device__ __forceinline__ float2 unpack2(u64 v) {
    return make_float2(__uint_as_float((unsigned)v), __uint_as_float((unsigned)(v >> 32)));
}

// ============================ exact top-k (+trailing weight-pack block) ============================
static __device__ __forceinline__ void warp_merge(
    u64 &topent, u64 &thrkey, int &bcnt, u64 (*buf)[32], int lane)
{
    u64 v[BUFD];
#pragma unroll
    for (int s = 0; s < BUFD; s++) v[s] = (s < bcnt) ? buf[s][lane] : ~0ULL;
    u64 oldtop = topent;
    u64 newtop = ~0ULL;
#pragma unroll 1
    for (int r = 0; r < SEL; r++) {
        u64 lm = oldtop;
#pragma unroll
        for (int s = 0; s < BUFD; s++) lm = umin64(lm, v[s]);
#pragma unroll
        for (int o = 16; o > 0; o >>= 1)
            lm = umin64(lm, __shfl_xor_sync(0xffffffffu, lm, o));
        if (oldtop == lm) oldtop = ~0ULL;
#pragma unroll
        for (int s = 0; s < BUFD; s++) if (v[s] == lm) v[s] = ~0ULL;
        if (lane == r) newtop = lm;
        thrkey = lm;
    }
    topent = newtop;
    bcnt = 0;
}

__global__ __launch_bounds__(32 * TWPB) void topk_kernel(
    const float4* __restrict__ states,
    const float* __restrict__ W1, const float* __restrict__ W2,
    const float* __restrict__ W3)
{
    // trailing block: pack weights (touches nothing the topk blocks read)
    if (blockIdx.x == TOPK_BLOCKS) {
        for (int t = threadIdx.x; t < 4096; t += 32 * TWPB) {
            int i = t >> 5, lane = t & 31;
            g_W3p[t] = make_float2(W3[lane * 128 + i], W3[(lane + 32) * 128 + i]);
            if (t < 2048)
                g_W2p4[t] = make_float4(W2[lane * 64 + i],        W2[(lane + 32) * 64 + i],
                                        W2[(lane + 64) * 64 + i], W2[(lane + 96) * 64 + i]);
            if (t < 192)
                g_W1p[t] = make_float2(W1[lane * 6 + i], W1[(lane + 32) * 6 + i]);
        }
        return;
    }

    __shared__ float2 sxy[N_AGENTS];       // 32 KB, packed (x,y)
    __shared__ u64 sbuf[TWPB][BUFD][32];   // 16 KB

    for (int j = threadIdx.x; j < N_AGENTS; j += 32 * TWPB) {
        float4 s = states[j];
        sxy[j] = make_float2(s.x, s.y);
    }
    __syncthreads();

    const int warp = threadIdx.x >> 5;
    const int lane = threadIdx.x & 31;
    const int row  = blockIdx.x * TWPB + warp;
    const float xi = sxy[row].x, yi = sxy[row].y;
    const float4* xy4 = reinterpret_cast<const float4*>(sxy);

    u64 topent = ~0ULL, thrkey = ~0ULL;
    int bcnt = 0;

    // ---- warm start: exact top-16 of first 128 candidates ----
    {
        float4 p0 = xy4[2 * lane];
        float4 p1 = xy4[2 * lane + 1];
        int j0 = 4 * lane;
        float dxa = __fsub_rn(xi, p0.x), dya = __fsub_rn(yi, p0.y);
        float d2a = __fadd_rn(__fadd_rn(__fmul_rn(dxa, dxa), EPSC),
                              __fadd_rn(__fmul_rn(dya, dya), EPSC));
        float dxb = __fsub_rn(xi, p0.z), dyb = __fsub_rn(yi, p0.w);
        float d2b = __fadd_rn(__fadd_rn(__fmul_rn(dxb, dxb), EPSC),
                              __fadd_rn(__fmul_rn(dyb, dyb), EPSC));
        float dxc = __fsub_rn(xi, p1.x), dyc = __fsub_rn(yi, p1.y);
        float d2c = __fadd_rn(__fadd_rn(__fmul_rn(dxc, dxc), EPSC),
                              __fadd_rn(__fmul_rn(dyc, dyc), EPSC));
        float dxd = __fsub_rn(xi, p1.z), dyd = __fsub_rn(yi, p1.w);
        float d2d = __fadd_rn(__fadd_rn(__fmul_rn(dxd, dxd), EPSC),
                              __fadd_rn(__fmul_rn(dyd, dyd), EPSC));
        topent = ((u64)__float_as_uint(d2a) << 32) | (unsigned)j0;
        sbuf[warp][0][lane] = ((u64)__float_as_uint(d2b) << 32) | (unsigned)(j0 + 1);
        sbuf[warp][1][lane] = ((u64)__float_as_uint(d2c) << 32) | (unsigned)(j0 + 2);
        sbuf[warp][2][lane] = ((u64)__float_as_uint(d2d) << 32) | (unsigned)(j0 + 3);
        bcnt = 3;
        warp_merge(topent, thrkey, bcnt, sbuf[warp], lane);
    }
    // float threshold: d2 <= thrf is a conservative-exact push filter
    // (d2 > 0 so float bits are monotone; equal-d2 extras are culled by the merge)
    float thrf = __uint_as_float((unsigned)(thrkey >> 32));

#pragma unroll 1
    for (int m = 1; m < N_AGENTS / 128; m++) {
        float4 p0 = xy4[m * 64 + 2 * lane];      // candidates j0..j0+1
        float4 p1 = xy4[m * 64 + 2 * lane + 1];  // candidates j0+2..j0+3
        int j0 = m * 128 + 4 * lane;
        float dxa = __fsub_rn(xi, p0.x), dya = __fsub_rn(yi, p0.y);
        float d2a = __fadd_rn(__fadd_rn(__fmul_rn(dxa, dxa), EPSC),
                              __fadd_rn(__fmul_rn(dya, dya), EPSC));
        float dxb = __fsub_rn(xi, p0.z), dyb = __fsub_rn(yi, p0.w);
        float d2b = __fadd_rn(__fadd_rn(__fmul_rn(dxb, dxb), EPSC),
                              __fadd_rn(__fmul_rn(dyb, dyb), EPSC));
        float dxc = __fsub_rn(xi, p1.x), dyc = __fsub_rn(yi, p1.y);
        float d2c = __fadd_rn(__fadd_rn(__fmul_rn(dxc, dxc), EPSC),
                              __fadd_rn(__fmul_rn(dyc, dyc), EPSC));
        float dxd = __fsub_rn(xi, p1.z), dyd = __fsub_rn(yi, p1.w);
        float d2d = __fadd_rn(__fadd_rn(__fmul_rn(dxd, dxd), EPSC),
                              __fadd_rn(__fmul_rn(dyd, dyd), EPSC));
        if (d2a <= thrf) {
            sbuf[warp][bcnt][lane] = ((u64)__float_as_uint(d2a) << 32) | (unsigned)j0;
            bcnt++;
        }
        if (d2b <= thrf) {
            sbuf[warp][bcnt][lane] = ((u64)__float_as_uint(d2b) << 32) | (unsigned)(j0 + 1);
            bcnt++;
        }
        if (d2c <= thrf) {
            sbuf[warp][bcnt][lane] = ((u64)__float_as_uint(d2c) << 32) | (unsigned)(j0 + 2);
            bcnt++;
        }
        if (d2d <= thrf) {
            sbuf[warp][bcnt][lane] = ((u64)__float_as_uint(d2d) << 32) | (unsigned)(j0 + 3);
            bcnt++;
        }
        if (__ballot_sync(0xffffffffu, bcnt > BUFD - 4)) {
            warp_merge(topent, thrkey, bcnt, sbuf[warp], lane);
            thrf = __uint_as_float((unsigned)(thrkey >> 32));
        }
    }
    if (__ballot_sync(0xffffffffu, bcnt > 0))
        warp_merge(topent, thrkey, bcnt, sbuf[warp], lane);

    // re-rank survivors by (dn, idx) — JAX top_k tie semantics
    float d2v = __uint_as_float((unsigned)(topent >> 32));
    int   jv  = (int)(unsigned)(topent & 0xffffffffu);
    float dnv = __fsqrt_rn(d2v);
    int rank = 0;
#pragma unroll
    for (int ml = 0; ml < SEL; ml++) {
        float dm = __shfl_sync(0xffffffffu, dnv, ml);
        int   jm = __shfl_sync(0xffffffffu, jv,  ml);
        if (ml != lane && (dm < dnv || (dm == dnv && jm < jv))) rank++;
    }
    if (lane < SEL && rank < TOPK) {
        g_idx[row * TOPK + rank] = jv;
        g_dn [row * TOPK + rank] = dnv;
    }
}

// ============ MLP: full agent per warp, single-pass layer 2 ============
#define WARP_FLOATS 2376
__global__ __launch_bounds__(128) void mlp_kernel(
    const float4* __restrict__ states,
    const float* __restrict__ b1, const float* __restrict__ b2,
    const float* __restrict__ b3,
    const float* __restrict__ W4, const float* __restrict__ b4,
    float* __restrict__ out, int out_size)
{
    __shared__ alignas(16) float smem[4][WARP_FLOATS];   // 38016 B total
    const int t = threadIdx.x;
    const int w = t >> 5;
    const int lane = t & 31;
    const int a = blockIdx.x * 4 + w;

    float* zB = smem[w];           // [128][12]; aliases: xs [12][8] (early), z3t [12][68] (late)
    float* zA = smem[w] + 1536;    // [64][12]
    float* A1 = smem[w] + 2304;    // [6][12]
    float* xs = zB;                // staging (dead before zB written)
    float* z3t = zB;

    float maskr = 0.0f;
    if (lane < TOPK) {
        int   idx = g_idx[a * TOPK + lane];
        float dn  = g_dn [a * TOPK + lane];
        float4 si = states[a];
        float4 sj = states[idx];
        xs[lane * 8 + 0] = __fsub_rn(si.x, sj.x);
        xs[lane * 8 + 1] = __fsub_rn(si.y, sj.y);
        xs[lane * 8 + 2] = __fsub_rn(si.z, sj.z);
        xs[lane * 8 + 3] = __fsub_rn(si.w, sj.w);
        xs[lane * 8 + 4] = (idx == a) ? 1.0f : 0.0f;
        xs[lane * 8 + 5] = __fsub_rn(dn, 0.8f);
        maskr = (dn <= 1.0f) ? 1.0f : 0.0f;
    }
    __syncwarp();
    // scrambled reshape: h0[i][l] = xs[2i + l/6][l % 6]
    if (lane < TOPK) {
        int half = lane / 6, cc = lane % 6;
#pragma unroll
        for (int i = 0; i < 6; i++)
            A1[i * 12 + lane] = xs[(2 * i + half) * 8 + cc];
    }
    __syncwarp();

    // ---- layer 1: 6 -> 64, 2 outputs/lane ----
    {
        u64 acc[12];
        u64 bb0 = pack2(b1[lane]), bb1 = pack2(b1[lane + 32]);
#pragma unroll
        for (int p = 0; p < 6; p++) { acc[p] = bb0; acc[6 + p] = bb1; }
#pragma unroll
        for (int i = 0; i < 6; i++) {
            float2 wv = g_W1p[i * 32 + lane];
            u64 w0 = pack2(wv.x), w1 = pack2(wv.y);
            const ulonglong2* r = reinterpret_cast<const ulonglong2*>(A1 + i * 12);
            ulonglong2 q0 = r[0], q1 = r[1], q2 = r[2];
            ffma2(acc[0], w0, q0.x); ffma2(acc[1], w0, q0.y);
            ffma2(acc[2], w0, q1.x); ffma2(acc[3], w0, q1.y);
            ffma2(acc[4], w0, q2.x); ffma2(acc[5], w0, q2.y);
            ffma2(acc[6], w1, q0.x); ffma2(acc[7], w1, q0.y);
            ffma2(acc[8], w1, q1.x); ffma2(acc[9], w1, q1.y);
            ffma2(acc[10], w1, q2.x); ffma2(acc[11], w1, q2.y);
        }
        float2* zA2 = reinterpret_cast<float2*>(zA);
#pragma unroll
        for (int p = 0; p < 6; p++) {
            float2 u = unpack2(acc[p]);
            zA2[lane * 6 + p] = make_float2(fmaxf(u.x, 0.f), fmaxf(u.y, 0.f));
            float2 v = unpack2(acc[6 + p]);
            zA2[(lane + 32) * 6 + p] = make_float2(fmaxf(v.x, 0.f), fmaxf(v.y, 0.f));
        }
    }
    __syncwarp();   // xs dead; zB writable

    // ---- layer 2: 64 -> 128, 4 outputs/lane, single pass ----
    {
        u64 acc[24];
#pragma unroll
        for (int q = 0; q < 4; q++) {
            u64 bb = pack2(b2[lane + 32 * q]);
#pragma unroll
            for (int p = 0; p < 6; p++) acc[q * 6 + p] = bb;
        }
#pragma unroll 2
        for (int i = 0; i < 64; i++) {
            float4 wv = g_W2p4[i * 32 + lane];
            u64 w0 = pack2(wv.x), w1 = pack2(wv.y), w2 = pack2(wv.z), w3 = pack2(wv.w);
            const ulonglong2* r = reinterpret_cast<const ulonglong2*>(zA + i * 12);
            ulonglong2 q0 = r[0], q1 = r[1], q2 = r[2];
            ffma2(acc[0],  w0, q0.x); ffma2(acc[1],  w0, q0.y);
            ffma2(acc[2],  w0, q1.x); ffma2(acc[3],  w0, q1.y);
            ffma2(acc[4],  w0, q2.x); ffma2(acc[5],  w0, q2.y);
            ffma2(acc[6],  w1, q0.x); ffma2(acc[7],  w1, q0.y);
            ffma2(acc[8],  w1, q1.x); ffma2(acc[9],  w1, q1.y);
            ffma2(acc[10], w1, q2.x); ffma2(acc[11], w1, q2.y);
            ffma2(acc[12], w2, q0.x); ffma2(acc[13], w2, q0.y);
            ffma2(acc[14], w2, q1.x); ffma2(acc[15], w2, q1.y);
            ffma2(acc[16], w2, q2.x); ffma2(acc[17], w2, q2.y);
            ffma2(acc[18], w3, q0.x); ffma2(acc[19], w3, q0.y);
            ffma2(acc[20], w3, q1.x); ffma2(acc[21], w3, q1.y);
            ffma2(acc[22], w3, q2.x); ffma2(acc[23], w3, q2.y);
        }
        float2* zB2 = reinterpret_cast<float2*>(zB);
#pragma unroll
        for (int q = 0; q < 4; q++) {
#pragma unroll
            for (int p = 0; p < 6; p++) {
                float2 u = unpack2(acc[q * 6 + p]);
                zB2[(lane + 32 * q) * 6 + p] =
                    make_float2(fmaxf(u.x, 0.f), fmaxf(u.y, 0.f));
            }
        }
    }
    __syncwarp();

    // ---- layer 3: 128 -> 64, 2 outputs/lane; store transposed z3t[12][68] ----
    {
        u64 acc[12];
        u64 bb0 = pack2(b3[lane]), bb1 = pack2(b3[lane + 32]);
#pragma unroll
        for (int p = 0; p < 6; p++) { acc[p] = bb0; acc[6 + p] = bb1; }
#pragma unroll 4
        for (int i = 0; i < 128; i++) {
            float2 wv = g_W3p[i * 32 + lane];
            u64 w0 = pack2(wv.x), w1 = pack2(wv.y);
            const ulonglong2* r = reinterpret_cast<const ulonglong2*>(zB + i * 12);
            ulonglong2 q0 = r[0], q1 = r[1], q2 = r[2];
            ffma2(acc[0], w0, q0.x); ffma2(acc[1], w0, q0.y);
            ffma2(acc[2], w0, q1.x); ffma2(acc[3], w0, q1.y);
            ffma2(acc[4], w0, q2.x); ffma2(acc[5], w0, q2.y);
            ffma2(acc[6], w1, q0.x); ffma2(acc[7], w1, q0.y);
            ffma2(acc[8], w1, q1.x); ffma2(acc[9], w1, q1.y);
            ffma2(acc[10], w1, q2.x); ffma2(acc[11], w1, q2.y);
        }
        __syncwarp();   // all zB reads done before z3t (alias) stores
#pragma unroll
        for (int p = 0; p < 6; p++) {
            float2 u = unpack2(acc[p]);
            z3t[(2 * p)     * 68 + lane] = fmaxf(u.x, 0.f);
            z3t[(2 * p + 1) * 68 + lane] = fmaxf(u.y, 0.f);
            float2 v = unpack2(acc[6 + p]);
            z3t[(2 * p)     * 68 + lane + 32] = fmaxf(v.x, 0.f);
            z3t[(2 * p + 1) * 68 + lane + 32] = fmaxf(v.y, 0.f);
        }
    }
    __syncwarp();

    // ---- layer 4: 64 -> 1 per column, mask, write ----
    if (lane < TOPK) {
        const float4* zv = reinterpret_cast<const float4*>(z3t + lane * 68);
        const float4* wv = reinterpret_cast<const float4*>(W4);
        float a0 = b4[0], a1 = 0.f, a2 = 0.f, a3 = 0.f;
#pragma unroll
        for (int oc = 0; oc < 16; oc++) {
            float4 z = zv[oc];
            float4 ww = wv[oc];
            a0 = fmaf(ww.x, z.x, a0);
            a1 = fmaf(ww.y, z.y, a1);
            a2 = fmaf(ww.z, z.z, a2);
            a3 = fmaf(ww.w, z.w, a3);
        }
        float acc = (a0 + a1) + (a2 + a3);
        out[a * TOPK + lane] = acc * maskr;
        if (out_size >= 2 * N_AGENTS * TOPK)
            out[N_AGENTS * TOPK + a * TOPK + lane] = maskr;
    }
}

extern "C" void kernel_launch(void* const* d_in, const int* in_sizes, int n_in,
                              void* d_out, int out_size) {
    const float* states = (const float*)d_in[0];
    const float* W1 = (const float*)d_in[1];
    const float* b1 = (const float*)d_in[2];
    const float* W2 = (const float*)d_in[3];
    const float* b2 = (const float*)d_in[4];
    const float* W3 = (const float*)d_in[5];
    const float* b3 = (const float*)d_in[6];
    const float* W4 = (const float*)d_in[7];
    const float* b4 = (const float*)d_in[8];
    float* out = (float*)d_out;

    topk_kernel<<<TOPK_BLOCKS + 1, 32 * TWPB>>>((const float4*)states, W1, W2, W3);
    mlp_kernel<<<N_AGENTS / 4, 128>>>((const float4*)states,
                                      b1, b2, b3, W4, b4, out, out_size);
}